// round 4
// baseline (speedup 1.0000x reference)
#include <cuda_runtime.h>
#include <cuda_bf16.h>

// GraphConvolution: out = relu(segment_sum((x @ W)[src] * ew, dst))
// R3 changes:
//  - GEMM inner loop uses packed fma.rn.f32x2 (FFMA2): acc packed over M,
//    A-fragment reinterpreted as f32x2 pairs, B duplicated in smem.
//  - Gather loads edge records cooperatively (coalesced) and broadcasts via
//    shfl; unrolled 16-edge chunks give 16-deep LDG batching.

#define N_NODES_MAX 100000
#define E_MAX       1600000
#define IN_F 256
#define OUT_F 64

#define SCAN_B 512
#define NBLK_MAX ((N_NODES_MAX + SCAN_B - 1) / SCAN_B)

__device__ float              g_support[N_NODES_MAX * OUT_F];
__device__ unsigned long long g_edges[E_MAX];
__device__ int                g_counts[N_NODES_MAX];
__device__ int                g_offs[N_NODES_MAX];
__device__ int                g_cursor[N_NODES_MAX];
__device__ int                g_blksum[NBLK_MAX];

// ---------------- packed f32x2 helpers ----------------
__device__ __forceinline__ unsigned long long ffma2(
    unsigned long long a, unsigned long long b, unsigned long long c)
{
    unsigned long long d;
    asm("fma.rn.f32x2 %0, %1, %2, %3;" : "=l"(d) : "l"(a), "l"(b), "l"(c));
    return d;
}
__device__ __forceinline__ unsigned long long dup2(float v) {
    unsigned long long r;
    asm("mov.b64 %0, {%1, %1};" : "=l"(r) : "r"(__float_as_uint(v)));
    return r;
}
__device__ __forceinline__ float lo32(unsigned long long v) {
    return __uint_as_float((unsigned int)v);
}
__device__ __forceinline__ float hi32(unsigned long long v) {
    return __uint_as_float((unsigned int)(v >> 32));
}

// ---------------- GEMM: 64x64 tile, 4x4 thread tile, BK=32, FFMA2 ----------------
#define BM 64
#define BN 64
#define BK 32
#define APAD 68

__global__ __launch_bounds__(256) void gemm_kernel(
    const float* __restrict__ x, const float* __restrict__ w,
    float* __restrict__ sup, int N)
{
    __shared__ float              As[BK * APAD];   // As[k][m]
    __shared__ unsigned long long Bs2[BK * BN];    // duplicated {b,b} per value

    const int tid = threadIdx.x;
    const int block_row = blockIdx.x * BM;
    const int tm = (tid >> 4) << 2;
    const int tn = (tid & 15) << 2;

    unsigned long long acc2[2][4];   // [m-pair][n], each packed {m_even, m_odd}
#pragma unroll
    for (int i = 0; i < 2; i++)
#pragma unroll
        for (int j = 0; j < 4; j++) acc2[i][j] = 0ULL;

    for (int k0 = 0; k0 < IN_F; k0 += BK) {
        // ---- A tile: 64 rows x 32 k, transposed to As[k][m] ----
#pragma unroll
        for (int i = 0; i < 2; i++) {
            int idx = tid * 2 + i;
            int row = idx >> 3;
            int kc  = idx & 7;
            int grow = block_row + row;
            float4 f = make_float4(0.f, 0.f, 0.f, 0.f);
            if (grow < N)
                f = *reinterpret_cast<const float4*>(&x[(size_t)grow * IN_F + k0 + kc * 4]);
            As[(kc * 4 + 0) * APAD + row] = f.x;
            As[(kc * 4 + 1) * APAD + row] = f.y;
            As[(kc * 4 + 2) * APAD + row] = f.z;
            As[(kc * 4 + 3) * APAD + row] = f.w;
        }
        // ---- B tile duplicated: Bs2[k][n] = {b, b} ----
#pragma unroll
        for (int i = 0; i < 2; i++) {
            int idx = tid * 2 + i;
            int krow = idx >> 4;
            int nc   = idx & 15;
            float4 f = *reinterpret_cast<const float4*>(&w[(size_t)(k0 + krow) * OUT_F + nc * 4]);
            unsigned long long* bp = &Bs2[krow * BN + nc * 4];
            bp[0] = dup2(f.x);
            bp[1] = dup2(f.y);
            bp[2] = dup2(f.z);
            bp[3] = dup2(f.w);
        }
        __syncthreads();

#pragma unroll
        for (int k = 0; k < BK; k++) {
            // a: 4 consecutive m values -> two packed f32x2 (no pack ops)
            ulonglong2 av = *reinterpret_cast<const ulonglong2*>(&As[k * APAD + tm]);
            ulonglong2 b01 = *reinterpret_cast<const ulonglong2*>(&Bs2[k * BN + tn]);
            ulonglong2 b23 = *reinterpret_cast<const ulonglong2*>(&Bs2[k * BN + tn + 2]);
            unsigned long long bd[4] = {b01.x, b01.y, b23.x, b23.y};
#pragma unroll
            for (int j = 0; j < 4; j++) {
                acc2[0][j] = ffma2(av.x, bd[j], acc2[0][j]);
                acc2[1][j] = ffma2(av.y, bd[j], acc2[1][j]);
            }
        }
        __syncthreads();
    }

    // epilogue: unpack 2 rows per m-pair
#pragma unroll
    for (int mi = 0; mi < 2; mi++) {
        int r0 = block_row + tm + mi * 2;
        if (r0 < N) {
            float4 v = make_float4(lo32(acc2[mi][0]), lo32(acc2[mi][1]),
                                   lo32(acc2[mi][2]), lo32(acc2[mi][3]));
            *reinterpret_cast<float4*>(&sup[(size_t)r0 * OUT_F + tn]) = v;
        }
        if (r0 + 1 < N) {
            float4 v = make_float4(hi32(acc2[mi][0]), hi32(acc2[mi][1]),
                                   hi32(acc2[mi][2]), hi32(acc2[mi][3]));
            *reinterpret_cast<float4*>(&sup[(size_t)(r0 + 1) * OUT_F + tn]) = v;
        }
    }
}

// ---------------- CSR build ----------------
__global__ void zero_counts_kernel(int* __restrict__ counts, int N) {
    int i = blockIdx.x * blockDim.x + threadIdx.x;
    if (i < N) counts[i] = 0;
}

__global__ void hist_kernel(const int* __restrict__ dst, int* __restrict__ counts, int E) {
    int e = blockIdx.x * blockDim.x + threadIdx.x;
    if (e < E) atomicAdd(&counts[dst[e]], 1);
}

__global__ __launch_bounds__(SCAN_B) void scan_block_kernel(
    const int* __restrict__ counts, int* __restrict__ offs,
    int* __restrict__ blksum, int N)
{
    __shared__ int sh[SCAN_B];
    int gid = blockIdx.x * SCAN_B + threadIdx.x;
    int v = (gid < N) ? counts[gid] : 0;
    sh[threadIdx.x] = v;
    __syncthreads();
#pragma unroll
    for (int d = 1; d < SCAN_B; d <<= 1) {
        int t = (threadIdx.x >= d) ? sh[threadIdx.x - d] : 0;
        __syncthreads();
        sh[threadIdx.x] += t;
        __syncthreads();
    }
    if (gid < N) offs[gid] = sh[threadIdx.x] - v;
    if (threadIdx.x == SCAN_B - 1) blksum[blockIdx.x] = sh[SCAN_B - 1];
}

__global__ __launch_bounds__(256) void scan_top_kernel(int* __restrict__ blksum, int nb) {
    __shared__ int sh[256];
    int v = (threadIdx.x < nb) ? blksum[threadIdx.x] : 0;
    sh[threadIdx.x] = v;
    __syncthreads();
#pragma unroll
    for (int d = 1; d < 256; d <<= 1) {
        int t = (threadIdx.x >= d) ? sh[threadIdx.x - d] : 0;
        __syncthreads();
        sh[threadIdx.x] += t;
        __syncthreads();
    }
    if (threadIdx.x < nb) blksum[threadIdx.x] = sh[threadIdx.x] - v;
}

__global__ void scan_add_kernel(int* __restrict__ offs, const int* __restrict__ blksum,
                                int* __restrict__ cursor, int N)
{
    int gid = blockIdx.x * blockDim.x + threadIdx.x;
    if (gid < N) {
        int o = offs[gid] + blksum[gid / SCAN_B];
        offs[gid] = o;
        cursor[gid] = o;
    }
}

__global__ void sort_scatter_kernel(
    const int* __restrict__ src, const int* __restrict__ dst,
    const float* __restrict__ ew, int* __restrict__ cursor,
    unsigned long long* __restrict__ es, int E)
{
    int e = blockIdx.x * blockDim.x + threadIdx.x;
    if (e < E) {
        int d = dst[e];
        int pos = atomicAdd(&cursor[d], 1);
        unsigned long long p = (unsigned int)src[e]
            | ((unsigned long long)__float_as_uint(ew[e]) << 32);
        es[pos] = p;
    }
}

// ---------------- gather + relu : 16 lanes/node, shfl-broadcast edges ----------------
__global__ __launch_bounds__(256) void gather_kernel(
    const float* __restrict__ sup,
    const unsigned long long* __restrict__ es,
    const int* __restrict__ offs, const int* __restrict__ counts,
    float* __restrict__ out, int N)
{
    int group = threadIdx.x >> 4;
    int lane  = threadIdx.x & 15;
    int node = blockIdx.x * 16 + group;
    if (node >= N) return;

    // mask of this thread's 16-lane segment within the warp
    unsigned int mask = 0xFFFFu << (threadIdx.x & 16);

    int start = offs[node];
    int deg   = counts[node];

    float4 acc = make_float4(0.f, 0.f, 0.f, 0.f);

    for (int base = 0; base < deg; base += 16) {
        int rem = deg - base;
        unsigned long long p = 0;
        if (lane < rem) p = __ldg(&es[start + base + lane]);

        if (rem >= 16) {
#pragma unroll
            for (int j = 0; j < 16; j++) {
                unsigned long long pj = __shfl_sync(mask, p, j, 16);
                int   s = (int)(unsigned int)pj;
                float wgt = __uint_as_float((unsigned int)(pj >> 32));
                float4 v = *reinterpret_cast<const float4*>(&sup[(size_t)s * OUT_F + lane * 4]);
                acc.x = fmaf(v.x, wgt, acc.x);
                acc.y = fmaf(v.y, wgt, acc.y);
                acc.z = fmaf(v.z, wgt, acc.z);
                acc.w = fmaf(v.w, wgt, acc.w);
            }
        } else {
            for (int j = 0; j < rem; j++) {
                unsigned long long pj = __shfl_sync(mask, p, j, 16);
                int   s = (int)(unsigned int)pj;
                float wgt = __uint_as_float((unsigned int)(pj >> 32));
                float4 v = *reinterpret_cast<const float4*>(&sup[(size_t)s * OUT_F + lane * 4]);
                acc.x = fmaf(v.x, wgt, acc.x);
                acc.y = fmaf(v.y, wgt, acc.y);
                acc.z = fmaf(v.z, wgt, acc.z);
                acc.w = fmaf(v.w, wgt, acc.w);
            }
        }
    }

    acc.x = fmaxf(acc.x, 0.f);
    acc.y = fmaxf(acc.y, 0.f);
    acc.z = fmaxf(acc.z, 0.f);
    acc.w = fmaxf(acc.w, 0.f);
    *reinterpret_cast<float4*>(&out[(size_t)node * OUT_F + lane * 4]) = acc;
}

extern "C" void kernel_launch(void* const* d_in, const int* in_sizes, int n_in,
                              void* d_out, int out_size)
{
    const float* x    = (const float*)d_in[0];
    const float* w    = (const float*)d_in[1];
    const int*   src  = (const int*)d_in[2];
    const int*   dst  = (const int*)d_in[3];
    const float* ew   = (const float*)d_in[4];
    float* out = (float*)d_out;

    const int N = in_sizes[0] / IN_F;
    const int E = in_sizes[2];

    float* sup;                cudaGetSymbolAddress((void**)&sup, g_support);
    unsigned long long* es;    cudaGetSymbolAddress((void**)&es, g_edges);
    int* counts;               cudaGetSymbolAddress((void**)&counts, g_counts);
    int* offs;                 cudaGetSymbolAddress((void**)&offs, g_offs);
    int* cursor;               cudaGetSymbolAddress((void**)&cursor, g_cursor);
    int* blksum;               cudaGetSymbolAddress((void**)&blksum, g_blksum);

    const int nb = (N + SCAN_B - 1) / SCAN_B;

    // 1) GEMM
    gemm_kernel<<<(N + BM - 1) / BM, 256>>>(x, w, sup, N);

    // 2) CSR build
    zero_counts_kernel<<<(N + 255) / 256, 256>>>(counts, N);
    hist_kernel<<<(E + 255) / 256, 256>>>(dst, counts, E);
    scan_block_kernel<<<nb, SCAN_B>>>(counts, offs, blksum, N);
    scan_top_kernel<<<1, 256>>>(blksum, nb);
    scan_add_kernel<<<(N + 255) / 256, 256>>>(offs, blksum, cursor, N);
    sort_scatter_kernel<<<(E + 255) / 256, 256>>>(src, dst, ew, cursor, es, E);

    // 3) gather + relu
    gather_kernel<<<(N + 15) / 16, 256>>>(sup, es, offs, counts, out, N);
}

// round 6
// speedup vs baseline: 1.6799x; 1.6799x over previous
#include <cuda_runtime.h>
#include <cuda_bf16.h>
#include <cstdint>

// GraphConvolution: out = relu(segment_sum((x @ W)[src] * ew, dst))
// R6: GEMM via warp-level mma.sync tf32 split-precision (compiles for sm_103,
//     no tcgen05). 3 products: ahi*bhi + ahi*blo + alo*bhi, fp32 accumulate.
//     CSR build + gather verbatim R3.

#define N_NODES_MAX 100000
#define E_MAX       1600000
#define IN_F 256
#define OUT_F 64

#define SCAN_B 512
#define NBLK_MAX ((N_NODES_MAX + SCAN_B - 1) / SCAN_B)

__device__ float              g_support[N_NODES_MAX * OUT_F];
__device__ unsigned long long g_edges[E_MAX];
__device__ int                g_counts[N_NODES_MAX];
__device__ int                g_offs[N_NODES_MAX];
__device__ int                g_cursor[N_NODES_MAX];
__device__ int                g_blksum[NBLK_MAX];

// ==================== tf32 helpers ====================
__device__ __forceinline__ uint32_t cvt_tf32(float f) {
    uint32_t r;
    asm("cvt.rna.tf32.f32 %0, %1;" : "=r"(r) : "f"(f));
    return r;
}

__device__ __forceinline__ void mma_tf32(float4& d,
    uint32_t a0, uint32_t a1, uint32_t a2, uint32_t a3,
    uint32_t b0, uint32_t b1)
{
    asm volatile(
        "mma.sync.aligned.m16n8k8.row.col.f32.tf32.tf32.f32 "
        "{%0,%1,%2,%3}, {%4,%5,%6,%7}, {%8,%9}, {%0,%1,%2,%3};"
        : "+f"(d.x), "+f"(d.y), "+f"(d.z), "+f"(d.w)
        : "r"(a0), "r"(a1), "r"(a2), "r"(a3), "r"(b0), "r"(b1));
}

// ==================== GEMM: 256 rows/CTA, 512 threads, tf32 mma.sync ==========
// B table in smem: for each (kt, nt, g, tig): float4 {bh0, bh1, bl0, bl1}
// where k0 = kt*8 + tig*2, k1 = k0+1 (k-permutation applied identically on A),
// n = nt*8 + g. 32*8*8*4 entries * 16B = 128KB.
#define KT_N   (IN_F / 8)        // 32
#define NT_N   (OUT_F / 8)       // 8
#define BTAB_ENTRIES (KT_N * NT_N * 8 * 4)
#define BTAB_BYTES   (BTAB_ENTRIES * 16)

__global__ __launch_bounds__(512, 1) void gemm_mma_kernel(
    const float* __restrict__ x, const float* __restrict__ w,
    float* __restrict__ sup, int N)
{
    extern __shared__ float4 Bs[];   // [kt][nt][g][tig]

    const int tid  = threadIdx.x;
    const int wid  = tid >> 5;
    const int lane = tid & 31;
    const int g    = lane >> 2;      // groupID 0..7
    const int tig  = lane & 3;       // thread-in-group 0..3

    // ---- build split-B table (once per CTA) ----
    for (int idx = tid; idx < BTAB_ENTRIES; idx += 512) {
        int t4 = idx & 3;
        int gg = (idx >> 2) & 7;
        int nt = (idx >> 5) & 7;
        int kt = idx >> 8;
        int k0 = kt * 8 + t4 * 2;
        int n  = nt * 8 + gg;
        float w0 = w[(size_t)k0 * OUT_F + n];
        float w1 = w[(size_t)(k0 + 1) * OUT_F + n];
        uint32_t h0 = cvt_tf32(w0);
        uint32_t h1 = cvt_tf32(w1);
        uint32_t l0 = cvt_tf32(w0 - __uint_as_float(h0));
        uint32_t l1 = cvt_tf32(w1 - __uint_as_float(h1));
        Bs[idx] = make_float4(__uint_as_float(h0), __uint_as_float(h1),
                              __uint_as_float(l0), __uint_as_float(l1));
    }
    __syncthreads();

    // ---- per-warp tile: 16 rows x 64 cols ----
    const int warp_row = blockIdx.x * 256 + wid * 16;
    const int r0 = warp_row + g;
    const int r1 = r0 + 8;
    // clamp OOB rows to a valid address (results discarded at store time)
    const float* xr0 = x + (size_t)(r0 < N ? r0 : 0) * IN_F;
    const float* xr1 = x + (size_t)(r1 < N ? r1 : 0) * IN_F;

    float4 acc[NT_N];
#pragma unroll
    for (int nt = 0; nt < NT_N; nt++) acc[nt] = make_float4(0.f, 0.f, 0.f, 0.f);

#pragma unroll 2
    for (int kt = 0; kt < KT_N; kt++) {
        const int coff = kt * 8 + tig * 2;
        float2 va0 = __ldg(reinterpret_cast<const float2*>(xr0 + coff));
        float2 va1 = __ldg(reinterpret_cast<const float2*>(xr1 + coff));

        // A fragment (k-permuted to match B table): a0/a2 from row r0, a1/a3 from r1
        uint32_t ah0 = cvt_tf32(va0.x);
        uint32_t ah2 = cvt_tf32(va0.y);
        uint32_t ah1 = cvt_tf32(va1.x);
        uint32_t ah3 = cvt_tf32(va1.y);
        uint32_t al0 = cvt_tf32(va0.x - __uint_as_float(ah0));
        uint32_t al2 = cvt_tf32(va0.y - __uint_as_float(ah2));
        uint32_t al1 = cvt_tf32(va1.x - __uint_as_float(ah1));
        uint32_t al3 = cvt_tf32(va1.y - __uint_as_float(ah3));

        const float4* brow = &Bs[((kt * NT_N) * 8 + g) * 4 + tig];
#pragma unroll
        for (int nt = 0; nt < NT_N; nt++) {
            float4 b = brow[nt * 32];   // (nt)*8*4 float4s ahead
            uint32_t bh0 = __float_as_uint(b.x);
            uint32_t bh1 = __float_as_uint(b.y);
            uint32_t bl0 = __float_as_uint(b.z);
            uint32_t bl1 = __float_as_uint(b.w);
            mma_tf32(acc[nt], ah0, ah1, ah2, ah3, bh0, bh1);
            mma_tf32(acc[nt], ah0, ah1, ah2, ah3, bl0, bl1);
            mma_tf32(acc[nt], al0, al1, al2, al3, bh0, bh1);
        }
    }

    // ---- epilogue: c0,c1 -> row r0 cols (nt*8 + tig*2, +1); c2,c3 -> row r1 ----
#pragma unroll
    for (int nt = 0; nt < NT_N; nt++) {
        int col = nt * 8 + tig * 2;
        if (r0 < N)
            *reinterpret_cast<float2*>(&sup[(size_t)r0 * OUT_F + col]) =
                make_float2(acc[nt].x, acc[nt].y);
        if (r1 < N)
            *reinterpret_cast<float2*>(&sup[(size_t)r1 * OUT_F + col]) =
                make_float2(acc[nt].z, acc[nt].w);
    }
}

// ==================== CSR build (verbatim R3) ====================
__global__ void zero_counts_kernel(int* __restrict__ counts, int N) {
    int i = blockIdx.x * blockDim.x + threadIdx.x;
    if (i < N) counts[i] = 0;
}

__global__ void hist_kernel(const int* __restrict__ dst, int* __restrict__ counts, int E) {
    int e = blockIdx.x * blockDim.x + threadIdx.x;
    if (e < E) atomicAdd(&counts[dst[e]], 1);
}

__global__ __launch_bounds__(SCAN_B) void scan_block_kernel(
    const int* __restrict__ counts, int* __restrict__ offs,
    int* __restrict__ blksum, int N)
{
    __shared__ int sh[SCAN_B];
    int gid = blockIdx.x * SCAN_B + threadIdx.x;
    int v = (gid < N) ? counts[gid] : 0;
    sh[threadIdx.x] = v;
    __syncthreads();
#pragma unroll
    for (int d = 1; d < SCAN_B; d <<= 1) {
        int t = (threadIdx.x >= d) ? sh[threadIdx.x - d] : 0;
        __syncthreads();
        sh[threadIdx.x] += t;
        __syncthreads();
    }
    if (gid < N) offs[gid] = sh[threadIdx.x] - v;
    if (threadIdx.x == SCAN_B - 1) blksum[blockIdx.x] = sh[SCAN_B - 1];
}

__global__ __launch_bounds__(256) void scan_top_kernel(int* __restrict__ blksum, int nb) {
    __shared__ int sh[256];
    int v = (threadIdx.x < nb) ? blksum[threadIdx.x] : 0;
    sh[threadIdx.x] = v;
    __syncthreads();
#pragma unroll
    for (int d = 1; d < 256; d <<= 1) {
        int t = (threadIdx.x >= d) ? sh[threadIdx.x - d] : 0;
        __syncthreads();
        sh[threadIdx.x] += t;
        __syncthreads();
    }
    if (threadIdx.x < nb) blksum[threadIdx.x] = sh[threadIdx.x] - v;
}

__global__ void scan_add_kernel(int* __restrict__ offs, const int* __restrict__ blksum,
                                int* __restrict__ cursor, int N)
{
    int gid = blockIdx.x * blockDim.x + threadIdx.x;
    if (gid < N) {
        int o = offs[gid] + blksum[gid / SCAN_B];
        offs[gid] = o;
        cursor[gid] = o;
    }
}

__global__ void sort_scatter_kernel(
    const int* __restrict__ src, const int* __restrict__ dst,
    const float* __restrict__ ew, int* __restrict__ cursor,
    unsigned long long* __restrict__ es, int E)
{
    int e = blockIdx.x * blockDim.x + threadIdx.x;
    if (e < E) {
        int d = dst[e];
        int pos = atomicAdd(&cursor[d], 1);
        unsigned long long p = (unsigned int)src[e]
            | ((unsigned long long)__float_as_uint(ew[e]) << 32);
        es[pos] = p;
    }
}

// ==================== gather + relu (verbatim R3) ====================
__global__ __launch_bounds__(256) void gather_kernel(
    const float* __restrict__ sup,
    const unsigned long long* __restrict__ es,
    const int* __restrict__ offs, const int* __restrict__ counts,
    float* __restrict__ out, int N)
{
    int group = threadIdx.x >> 4;
    int lane  = threadIdx.x & 15;
    int node = blockIdx.x * 16 + group;
    if (node >= N) return;

    int start = offs[node];
    int deg   = counts[node];
    int end   = start + deg;

    float4 acc = make_float4(0.f, 0.f, 0.f, 0.f);

    int e = start;
    for (; e + 2 <= end; e += 2) {
        unsigned long long p0 = __ldg(&es[e]);
        unsigned long long p1 = __ldg(&es[e + 1]);
        int   s0 = (int)(unsigned int)p0;
        float w0 = __uint_as_float((unsigned int)(p0 >> 32));
        int   s1 = (int)(unsigned int)p1;
        float w1 = __uint_as_float((unsigned int)(p1 >> 32));
        float4 v0 = *reinterpret_cast<const float4*>(&sup[(size_t)s0 * OUT_F + lane * 4]);
        float4 v1 = *reinterpret_cast<const float4*>(&sup[(size_t)s1 * OUT_F + lane * 4]);
        acc.x = fmaf(v0.x, w0, acc.x);
        acc.y = fmaf(v0.y, w0, acc.y);
        acc.z = fmaf(v0.z, w0, acc.z);
        acc.w = fmaf(v0.w, w0, acc.w);
        acc.x = fmaf(v1.x, w1, acc.x);
        acc.y = fmaf(v1.y, w1, acc.y);
        acc.z = fmaf(v1.z, w1, acc.z);
        acc.w = fmaf(v1.w, w1, acc.w);
    }
    if (e < end) {
        unsigned long long p0 = __ldg(&es[e]);
        int   s0 = (int)(unsigned int)p0;
        float w0 = __uint_as_float((unsigned int)(p0 >> 32));
        float4 v0 = *reinterpret_cast<const float4*>(&sup[(size_t)s0 * OUT_F + lane * 4]);
        acc.x = fmaf(v0.x, w0, acc.x);
        acc.y = fmaf(v0.y, w0, acc.y);
        acc.z = fmaf(v0.z, w0, acc.z);
        acc.w = fmaf(v0.w, w0, acc.w);
    }

    acc.x = fmaxf(acc.x, 0.f);
    acc.y = fmaxf(acc.y, 0.f);
    acc.z = fmaxf(acc.z, 0.f);
    acc.w = fmaxf(acc.w, 0.f);
    *reinterpret_cast<float4*>(&out[(size_t)node * OUT_F + lane * 4]) = acc;
}

extern "C" void kernel_launch(void* const* d_in, const int* in_sizes, int n_in,
                              void* d_out, int out_size)
{
    const float* x    = (const float*)d_in[0];
    const float* w    = (const float*)d_in[1];
    const int*   src  = (const int*)d_in[2];
    const int*   dst  = (const int*)d_in[3];
    const float* ew   = (const float*)d_in[4];
    float* out = (float*)d_out;

    const int N = in_sizes[0] / IN_F;
    const int E = in_sizes[2];

    float* sup;                cudaGetSymbolAddress((void**)&sup, g_support);
    unsigned long long* es;    cudaGetSymbolAddress((void**)&es, g_edges);
    int* counts;               cudaGetSymbolAddress((void**)&counts, g_counts);
    int* offs;                 cudaGetSymbolAddress((void**)&offs, g_offs);
    int* cursor;               cudaGetSymbolAddress((void**)&cursor, g_cursor);
    int* blksum;               cudaGetSymbolAddress((void**)&blksum, g_blksum);

    const int nb = (N + SCAN_B - 1) / SCAN_B;

    // 1) GEMM (tf32 mma.sync split-precision)
    cudaFuncSetAttribute(gemm_mma_kernel,
                         cudaFuncAttributeMaxDynamicSharedMemorySize, BTAB_BYTES);
    gemm_mma_kernel<<<(N + 255) / 256, 512, BTAB_BYTES>>>(x, w, sup, N);

    // 2) CSR build
    zero_counts_kernel<<<(N + 255) / 256, 256>>>(counts, N);
    hist_kernel<<<(E + 255) / 256, 256>>>(dst, counts, E);
    scan_block_kernel<<<nb, SCAN_B>>>(counts, offs, blksum, N);
    scan_top_kernel<<<1, 256>>>(blksum, nb);
    scan_add_kernel<<<(N + 255) / 256, 256>>>(offs, blksum, cursor, N);
    sort_scatter_kernel<<<(E + 255) / 256, 256>>>(src, dst, ew, cursor, es, E);

    // 3) gather + relu
    gather_kernel<<<(N + 15) / 16, 256>>>(sup, es, offs, counts, out, N);
}

// round 7
// speedup vs baseline: 1.9549x; 1.1637x over previous
#include <cuda_runtime.h>
#include <cuda_bf16.h>
#include <cstdint>

// GraphConvolution: out = relu(segment_sum((x @ W)[src] * ew, dst))
// R7: tf32 mma.sync GEMM with A staged through smem (batched LDG.128 loads fix
//     the DRAM-latency bound seen in R6). CSR build + gather verbatim R3.

#define N_NODES_MAX 100000
#define E_MAX       1600000
#define IN_F 256
#define OUT_F 64

#define SCAN_B 512
#define NBLK_MAX ((N_NODES_MAX + SCAN_B - 1) / SCAN_B)

__device__ float              g_support[N_NODES_MAX * OUT_F];
__device__ unsigned long long g_edges[E_MAX];
__device__ int                g_counts[N_NODES_MAX];
__device__ int                g_offs[N_NODES_MAX];
__device__ int                g_cursor[N_NODES_MAX];
__device__ int                g_blksum[NBLK_MAX];

// ==================== tf32 helpers ====================
__device__ __forceinline__ uint32_t cvt_tf32(float f) {
    uint32_t r;
    asm("cvt.rna.tf32.f32 %0, %1;" : "=r"(r) : "f"(f));
    return r;
}

__device__ __forceinline__ void mma_tf32(float4& d,
    uint32_t a0, uint32_t a1, uint32_t a2, uint32_t a3,
    uint32_t b0, uint32_t b1)
{
    asm volatile(
        "mma.sync.aligned.m16n8k8.row.col.f32.tf32.tf32.f32 "
        "{%0,%1,%2,%3}, {%4,%5,%6,%7}, {%8,%9}, {%0,%1,%2,%3};"
        : "+f"(d.x), "+f"(d.y), "+f"(d.z), "+f"(d.w)
        : "r"(a0), "r"(a1), "r"(a2), "r"(a3), "r"(b0), "r"(b1));
}

// ==================== GEMM config ====================
#define KT_N   (IN_F / 8)        // 32 k-tiles total
#define NT_N   (OUT_F / 8)       // 8 n-tiles
#define BTAB_ENTRIES (KT_N * NT_N * 8 * 4)
#define BTAB_BYTES   (BTAB_ENTRIES * 16)      // 128KB

#define ROWS_CTA 256
#define KB       64              // k per staged block
#define NKB      (IN_F / KB)     // 4
#define KT_PER_B (KB / 8)        // 8
#define ASTRIDE  68              // floats per row in smem (padded, 16B-aligned)
#define ATILE_BYTES (ROWS_CTA * ASTRIDE * 4)  // 69632
#define SMEM_TOTAL (BTAB_BYTES + ATILE_BYTES) // 200704

__global__ __launch_bounds__(512, 1) void gemm_mma_kernel(
    const float* __restrict__ x, const float* __restrict__ w,
    float* __restrict__ sup, int N)
{
    extern __shared__ char smem_raw[];
    float4* Bs = reinterpret_cast<float4*>(smem_raw);                 // [kt][nt][g][tig]
    float*  As = reinterpret_cast<float*>(smem_raw + BTAB_BYTES);     // [row][ASTRIDE]

    const int tid  = threadIdx.x;
    const int wid  = tid >> 5;
    const int lane = tid & 31;
    const int g    = lane >> 2;      // groupID 0..7
    const int tig  = lane & 3;       // thread-in-group 0..3

    // ---- build split-B table (once per CTA) ----
    for (int idx = tid; idx < BTAB_ENTRIES; idx += 512) {
        int t4 = idx & 3;
        int gg = (idx >> 2) & 7;
        int nt = (idx >> 5) & 7;
        int kt = idx >> 8;
        int k0 = kt * 8 + t4 * 2;
        int n  = nt * 8 + gg;
        float w0 = w[(size_t)k0 * OUT_F + n];
        float w1 = w[(size_t)(k0 + 1) * OUT_F + n];
        uint32_t h0 = cvt_tf32(w0);
        uint32_t h1 = cvt_tf32(w1);
        uint32_t l0 = cvt_tf32(w0 - __uint_as_float(h0));
        uint32_t l1 = cvt_tf32(w1 - __uint_as_float(h1));
        Bs[idx] = make_float4(__uint_as_float(h0), __uint_as_float(h1),
                              __uint_as_float(l0), __uint_as_float(l1));
    }

    const int row0 = blockIdx.x * ROWS_CTA;
    const int rloc0 = wid * 16 + g;          // local row for c0/c1
    const int rloc1 = rloc0 + 8;             // local row for c2/c3
    const int r0 = row0 + rloc0;
    const int r1 = row0 + rloc1;

    float4 acc[NT_N];
#pragma unroll
    for (int nt = 0; nt < NT_N; nt++) acc[nt] = make_float4(0.f, 0.f, 0.f, 0.f);

    __syncthreads();   // B table ready

    for (int kb = 0; kb < NKB; kb++) {
        // ---- stage A block: 256 rows x 64 cols, 8 independent LDG.128/thread ----
#pragma unroll
        for (int i = 0; i < 8; i++) {
            int idx = tid + i * 512;          // 0..4095
            int r  = idx >> 4;
            int c4 = idx & 15;
            int grow = row0 + r;
            float4 f = make_float4(0.f, 0.f, 0.f, 0.f);
            if (grow < N)
                f = __ldg(reinterpret_cast<const float4*>(
                        &x[(size_t)grow * IN_F + kb * KB + c4 * 4]));
            *reinterpret_cast<float4*>(&As[r * ASTRIDE + c4 * 4]) = f;
        }
        __syncthreads();

        // ---- 8 k-tiles from smem ----
#pragma unroll
        for (int ktl = 0; ktl < KT_PER_B; ktl++) {
            const int kt = kb * KT_PER_B + ktl;
            const int coff = ktl * 8 + tig * 2;
            float2 va0 = *reinterpret_cast<const float2*>(&As[rloc0 * ASTRIDE + coff]);
            float2 va1 = *reinterpret_cast<const float2*>(&As[rloc1 * ASTRIDE + coff]);

            uint32_t ah0 = cvt_tf32(va0.x);
            uint32_t ah2 = cvt_tf32(va0.y);
            uint32_t ah1 = cvt_tf32(va1.x);
            uint32_t ah3 = cvt_tf32(va1.y);
            uint32_t al0 = cvt_tf32(va0.x - __uint_as_float(ah0));
            uint32_t al2 = cvt_tf32(va0.y - __uint_as_float(ah2));
            uint32_t al1 = cvt_tf32(va1.x - __uint_as_float(ah1));
            uint32_t al3 = cvt_tf32(va1.y - __uint_as_float(ah3));

            const float4* brow = &Bs[((kt * NT_N) * 8 + g) * 4 + tig];
#pragma unroll
            for (int nt = 0; nt < NT_N; nt++) {
                float4 b = brow[nt * 32];
                uint32_t bh0 = __float_as_uint(b.x);
                uint32_t bh1 = __float_as_uint(b.y);
                uint32_t bl0 = __float_as_uint(b.z);
                uint32_t bl1 = __float_as_uint(b.w);
                mma_tf32(acc[nt], ah0, ah1, ah2, ah3, bh0, bh1);
                mma_tf32(acc[nt], ah0, ah1, ah2, ah3, bl0, bl1);
                mma_tf32(acc[nt], al0, al1, al2, al3, bh0, bh1);
            }
        }
        __syncthreads();
    }

    // ---- epilogue: c0,c1 -> row r0; c2,c3 -> row r1 ----
#pragma unroll
    for (int nt = 0; nt < NT_N; nt++) {
        int col = nt * 8 + tig * 2;
        if (r0 < N)
            *reinterpret_cast<float2*>(&sup[(size_t)r0 * OUT_F + col]) =
                make_float2(acc[nt].x, acc[nt].y);
        if (r1 < N)
            *reinterpret_cast<float2*>(&sup[(size_t)r1 * OUT_F + col]) =
                make_float2(acc[nt].z, acc[nt].w);
    }
}

// ==================== CSR build (verbatim R3) ====================
__global__ void zero_counts_kernel(int* __restrict__ counts, int N) {
    int i = blockIdx.x * blockDim.x + threadIdx.x;
    if (i < N) counts[i] = 0;
}

__global__ void hist_kernel(const int* __restrict__ dst, int* __restrict__ counts, int E) {
    int e = blockIdx.x * blockDim.x + threadIdx.x;
    if (e < E) atomicAdd(&counts[dst[e]], 1);
}

__global__ __launch_bounds__(SCAN_B) void scan_block_kernel(
    const int* __restrict__ counts, int* __restrict__ offs,
    int* __restrict__ blksum, int N)
{
    __shared__ int sh[SCAN_B];
    int gid = blockIdx.x * SCAN_B + threadIdx.x;
    int v = (gid < N) ? counts[gid] : 0;
    sh[threadIdx.x] = v;
    __syncthreads();
#pragma unroll
    for (int d = 1; d < SCAN_B; d <<= 1) {
        int t = (threadIdx.x >= d) ? sh[threadIdx.x - d] : 0;
        __syncthreads();
        sh[threadIdx.x] += t;
        __syncthreads();
    }
    if (gid < N) offs[gid] = sh[threadIdx.x] - v;
    if (threadIdx.x == SCAN_B - 1) blksum[blockIdx.x] = sh[SCAN_B - 1];
}

__global__ __launch_bounds__(256) void scan_top_kernel(int* __restrict__ blksum, int nb) {
    __shared__ int sh[256];
    int v = (threadIdx.x < nb) ? blksum[threadIdx.x] : 0;
    sh[threadIdx.x] = v;
    __syncthreads();
#pragma unroll
    for (int d = 1; d < 256; d <<= 1) {
        int t = (threadIdx.x >= d) ? sh[threadIdx.x - d] : 0;
        __syncthreads();
        sh[threadIdx.x] += t;
        __syncthreads();
    }
    if (threadIdx.x < nb) blksum[threadIdx.x] = sh[threadIdx.x] - v;
}

__global__ void scan_add_kernel(int* __restrict__ offs, const int* __restrict__ blksum,
                                int* __restrict__ cursor, int N)
{
    int gid = blockIdx.x * blockDim.x + threadIdx.x;
    if (gid < N) {
        int o = offs[gid] + blksum[gid / SCAN_B];
        offs[gid] = o;
        cursor[gid] = o;
    }
}

__global__ void sort_scatter_kernel(
    const int* __restrict__ src, const int* __restrict__ dst,
    const float* __restrict__ ew, int* __restrict__ cursor,
    unsigned long long* __restrict__ es, int E)
{
    int e = blockIdx.x * blockDim.x + threadIdx.x;
    if (e < E) {
        int d = dst[e];
        int pos = atomicAdd(&cursor[d], 1);
        unsigned long long p = (unsigned int)src[e]
            | ((unsigned long long)__float_as_uint(ew[e]) << 32);
        es[pos] = p;
    }
}

// ==================== gather + relu (verbatim R3) ====================
__global__ __launch_bounds__(256) void gather_kernel(
    const float* __restrict__ sup,
    const unsigned long long* __restrict__ es,
    const int* __restrict__ offs, const int* __restrict__ counts,
    float* __restrict__ out, int N)
{
    int group = threadIdx.x >> 4;
    int lane  = threadIdx.x & 15;
    int node = blockIdx.x * 16 + group;
    if (node >= N) return;

    int start = offs[node];
    int deg   = counts[node];
    int end   = start + deg;

    float4 acc = make_float4(0.f, 0.f, 0.f, 0.f);

    int e = start;
    for (; e + 2 <= end; e += 2) {
        unsigned long long p0 = __ldg(&es[e]);
        unsigned long long p1 = __ldg(&es[e + 1]);
        int   s0 = (int)(unsigned int)p0;
        float w0 = __uint_as_float((unsigned int)(p0 >> 32));
        int   s1 = (int)(unsigned int)p1;
        float w1 = __uint_as_float((unsigned int)(p1 >> 32));
        float4 v0 = *reinterpret_cast<const float4*>(&sup[(size_t)s0 * OUT_F + lane * 4]);
        float4 v1 = *reinterpret_cast<const float4*>(&sup[(size_t)s1 * OUT_F + lane * 4]);
        acc.x = fmaf(v0.x, w0, acc.x);
        acc.y = fmaf(v0.y, w0, acc.y);
        acc.z = fmaf(v0.z, w0, acc.z);
        acc.w = fmaf(v0.w, w0, acc.w);
        acc.x = fmaf(v1.x, w1, acc.x);
        acc.y = fmaf(v1.y, w1, acc.y);
        acc.z = fmaf(v1.z, w1, acc.z);
        acc.w = fmaf(v1.w, w1, acc.w);
    }
    if (e < end) {
        unsigned long long p0 = __ldg(&es[e]);
        int   s0 = (int)(unsigned int)p0;
        float w0 = __uint_as_float((unsigned int)(p0 >> 32));
        float4 v0 = *reinterpret_cast<const float4*>(&sup[(size_t)s0 * OUT_F + lane * 4]);
        acc.x = fmaf(v0.x, w0, acc.x);
        acc.y = fmaf(v0.y, w0, acc.y);
        acc.z = fmaf(v0.z, w0, acc.z);
        acc.w = fmaf(v0.w, w0, acc.w);
    }

    acc.x = fmaxf(acc.x, 0.f);
    acc.y = fmaxf(acc.y, 0.f);
    acc.z = fmaxf(acc.z, 0.f);
    acc.w = fmaxf(acc.w, 0.f);
    *reinterpret_cast<float4*>(&out[(size_t)node * OUT_F + lane * 4]) = acc;
}

extern "C" void kernel_launch(void* const* d_in, const int* in_sizes, int n_in,
                              void* d_out, int out_size)
{
    const float* x    = (const float*)d_in[0];
    const float* w    = (const float*)d_in[1];
    const int*   src  = (const int*)d_in[2];
    const int*   dst  = (const int*)d_in[3];
    const float* ew   = (const float*)d_in[4];
    float* out = (float*)d_out;

    const int N = in_sizes[0] / IN_F;
    const int E = in_sizes[2];

    float* sup;                cudaGetSymbolAddress((void**)&sup, g_support);
    unsigned long long* es;    cudaGetSymbolAddress((void**)&es, g_edges);
    int* counts;               cudaGetSymbolAddress((void**)&counts, g_counts);
    int* offs;                 cudaGetSymbolAddress((void**)&offs, g_offs);
    int* cursor;               cudaGetSymbolAddress((void**)&cursor, g_cursor);
    int* blksum;               cudaGetSymbolAddress((void**)&blksum, g_blksum);

    const int nb = (N + SCAN_B - 1) / SCAN_B;

    // 1) GEMM (tf32 mma.sync, smem-staged A)
    cudaFuncSetAttribute(gemm_mma_kernel,
                         cudaFuncAttributeMaxDynamicSharedMemorySize, SMEM_TOTAL);
    gemm_mma_kernel<<<(N + ROWS_CTA - 1) / ROWS_CTA, 512, SMEM_TOTAL>>>(x, w, sup, N);

    // 2) CSR build
    zero_counts_kernel<<<(N + 255) / 256, 256>>>(counts, N);
    hist_kernel<<<(E + 255) / 256, 256>>>(dst, counts, E);
    scan_block_kernel<<<nb, SCAN_B>>>(counts, offs, blksum, N);
    scan_top_kernel<<<1, 256>>>(blksum, nb);
    scan_add_kernel<<<(N + 255) / 256, 256>>>(offs, blksum, cursor, N);
    sort_scatter_kernel<<<(E + 255) / 256, 256>>>(src, dst, ew, cursor, es, E);

    // 3) gather + relu
    gather_kernel<<<(N + 15) / 16, 256>>>(sup, es, offs, counts, out, N);
}

// round 8
// speedup vs baseline: 2.6244x; 1.3425x over previous
#include <cuda_runtime.h>
#include <cuda_bf16.h>
#include <cstdint>

// GraphConvolution: out = relu(segment_sum((x @ W)[src] * ew, dst))
// R8: GEMM via mma.sync m16n8k16 bf16 split-3 (half the HMMA instructions of
//     R7's tf32 k8), cp.async double-buffered A staging. CSR + gather verbatim R3.

#define N_NODES_MAX 100000
#define E_MAX       1600000
#define IN_F 256
#define OUT_F 64

#define SCAN_B 512
#define NBLK_MAX ((N_NODES_MAX + SCAN_B - 1) / SCAN_B)

__device__ float              g_support[N_NODES_MAX * OUT_F];
__device__ unsigned long long g_edges[E_MAX];
__device__ int                g_counts[N_NODES_MAX];
__device__ int                g_offs[N_NODES_MAX];
__device__ int                g_cursor[N_NODES_MAX];
__device__ int                g_blksum[NBLK_MAX];

// ==================== helpers ====================
__device__ __forceinline__ uint32_t smem_u32(const void* p) {
    uint32_t a;
    asm("{ .reg .u64 t; cvta.to.shared.u64 t, %1; cvt.u32.u64 %0, t; }"
        : "=r"(a) : "l"(p));
    return a;
}

__device__ __forceinline__ void cp_async16(uint32_t dst, const void* src, int src_bytes) {
    asm volatile("cp.async.cg.shared.global [%0], [%1], 16, %2;"
                 :: "r"(dst), "l"(src), "r"(src_bytes));
}
#define CP_COMMIT() asm volatile("cp.async.commit_group;" ::: "memory")
#define CP_WAIT(n)  asm volatile("cp.async.wait_group %0;" :: "n"(n) : "memory")

__device__ __forceinline__ uint32_t bf2(float x, float y) {
    __nv_bfloat162 h = __floats2bfloat162_rn(x, y);
    return *reinterpret_cast<uint32_t*>(&h);
}
__device__ __forceinline__ float2 bf2f(uint32_t u) {
    __nv_bfloat162 h = *reinterpret_cast<__nv_bfloat162*>(&u);
    return __bfloat1622float2(h);
}

__device__ __forceinline__ void mma_bf16(float4& d,
    uint32_t a0, uint32_t a1, uint32_t a2, uint32_t a3,
    uint32_t b0, uint32_t b1)
{
    asm volatile(
        "mma.sync.aligned.m16n8k16.row.col.f32.bf16.bf16.f32 "
        "{%0,%1,%2,%3}, {%4,%5,%6,%7}, {%8,%9}, {%0,%1,%2,%3};"
        : "+f"(d.x), "+f"(d.y), "+f"(d.z), "+f"(d.w)
        : "r"(a0), "r"(a1), "r"(a2), "r"(a3), "r"(b0), "r"(b1));
}

// ==================== GEMM config ====================
#define KC_N   (IN_F / 16)       // 16 k-chunks total
#define NT_N   (OUT_F / 8)       // 8 n-tiles
// B table: [kc][nt][lane] -> float4 {bh0, bh1, bl0, bl1} (each u32 = bf16x2)
#define BTAB_ENTRIES (KC_N * NT_N * 32)
#define BTAB_BYTES   (BTAB_ENTRIES * 16)      // 65536

#define ROWS_CTA 256
#define KB       64              // k per staged block
#define NKB      (IN_F / KB)     // 4
#define KC_PER_B (KB / 16)       // 4 k-chunks per staged block
#define ASTRIDE  68              // floats per smem row (16B-aligned stride)
#define ATILE_BYTES (ROWS_CTA * ASTRIDE * 4)  // 69632
#define SMEM_TOTAL (BTAB_BYTES + 2 * ATILE_BYTES) // 204800

__global__ __launch_bounds__(512, 1) void gemm_mma_kernel(
    const float* __restrict__ x, const float* __restrict__ w,
    float* __restrict__ sup, int N)
{
    extern __shared__ char smem_raw[];
    float4* Bs = reinterpret_cast<float4*>(smem_raw);
    float*  As = reinterpret_cast<float*>(smem_raw + BTAB_BYTES);
    const uint32_t a_sbase = smem_u32(As);

    const int tid  = threadIdx.x;
    const int wid  = tid >> 5;
    const int lane = tid & 31;
    const int g    = lane >> 2;
    const int tig  = lane & 3;

    const int row0  = blockIdx.x * ROWS_CTA;
    const int rloc0 = wid * 16 + g;
    const int rloc1 = rloc0 + 8;
    const int r0 = row0 + rloc0;
    const int r1 = row0 + rloc1;

    // ---- stage loader: block kb -> buffer buf (cp.async, zero-fill OOB) ----
    auto stage = [&](int kb, int buf) {
        uint32_t abase = a_sbase + buf * ATILE_BYTES;
#pragma unroll
        for (int i = 0; i < 8; i++) {
            int idx = tid + i * 512;           // 0..4095
            int r  = idx >> 4;
            int c4 = idx & 15;
            int grow = row0 + r;
            uint32_t dst = abase + (uint32_t)(r * ASTRIDE + c4 * 4) * 4u;
            const float* srcp = &x[(size_t)(grow < N ? grow : 0) * IN_F + kb * KB + c4 * 4];
            cp_async16(dst, srcp, grow < N ? 16 : 0);
        }
    };

    // ---- build split-B table (bf16 hi/lo) ----
    for (int idx = tid; idx < BTAB_ENTRIES; idx += 512) {
        int ln = idx & 31;
        int nt = (idx >> 5) & 7;
        int kc = idx >> 8;                     // 0..15
        int gg  = ln >> 2;
        int tt  = ln & 3;
        int n  = nt * 8 + gg;
        int k0 = kc * 16 + 2 * tt;
        float w00 = w[(size_t)k0 * OUT_F + n];
        float w01 = w[(size_t)(k0 + 1) * OUT_F + n];
        float w10 = w[(size_t)(k0 + 8) * OUT_F + n];
        float w11 = w[(size_t)(k0 + 9) * OUT_F + n];
        uint32_t h0 = bf2(w00, w01);
        uint32_t h1 = bf2(w10, w11);
        float2 hf0 = bf2f(h0);
        float2 hf1 = bf2f(h1);
        uint32_t l0 = bf2(w00 - hf0.x, w01 - hf0.y);
        uint32_t l1 = bf2(w10 - hf1.x, w11 - hf1.y);
        Bs[idx] = make_float4(__uint_as_float(h0), __uint_as_float(h1),
                              __uint_as_float(l0), __uint_as_float(l1));
    }

    float4 acc[NT_N];
#pragma unroll
    for (int nt = 0; nt < NT_N; nt++) acc[nt] = make_float4(0.f, 0.f, 0.f, 0.f);

    // prefetch first A block
    stage(0, 0);
    CP_COMMIT();
    __syncthreads();   // B table also ready after this

    for (int kb = 0; kb < NKB; kb++) {
        if (kb + 1 < NKB) {
            stage(kb + 1, (kb + 1) & 1);
            CP_COMMIT();
            CP_WAIT(1);
        } else {
            CP_WAIT(0);
        }
        __syncthreads();

        const float* Ab = As + (kb & 1) * (ROWS_CTA * ASTRIDE);

#pragma unroll
        for (int kcl = 0; kcl < KC_PER_B; kcl++) {
            const int kc = kb * KC_PER_B + kcl;
            const int c0 = kcl * 16 + 2 * tig;

            float2 a00 = *reinterpret_cast<const float2*>(&Ab[rloc0 * ASTRIDE + c0]);
            float2 a08 = *reinterpret_cast<const float2*>(&Ab[rloc0 * ASTRIDE + c0 + 8]);
            float2 a10 = *reinterpret_cast<const float2*>(&Ab[rloc1 * ASTRIDE + c0]);
            float2 a18 = *reinterpret_cast<const float2*>(&Ab[rloc1 * ASTRIDE + c0 + 8]);

            uint32_t ah0 = bf2(a00.x, a00.y);   // row g,   cols k0,k0+1
            uint32_t ah1 = bf2(a10.x, a10.y);   // row g+8
            uint32_t ah2 = bf2(a08.x, a08.y);   // row g,   cols k0+8,k0+9
            uint32_t ah3 = bf2(a18.x, a18.y);   // row g+8
            float2 f0 = bf2f(ah0), f1 = bf2f(ah1), f2 = bf2f(ah2), f3 = bf2f(ah3);
            uint32_t al0 = bf2(a00.x - f0.x, a00.y - f0.y);
            uint32_t al1 = bf2(a10.x - f1.x, a10.y - f1.y);
            uint32_t al2 = bf2(a08.x - f2.x, a08.y - f2.y);
            uint32_t al3 = bf2(a18.x - f3.x, a18.y - f3.y);

            const float4* brow = &Bs[(kc * NT_N) * 32 + lane];
#pragma unroll
            for (int nt = 0; nt < NT_N; nt++) {
                float4 b = brow[nt * 32];
                uint32_t bh0 = __float_as_uint(b.x);
                uint32_t bh1 = __float_as_uint(b.y);
                uint32_t bl0 = __float_as_uint(b.z);
                uint32_t bl1 = __float_as_uint(b.w);
                mma_bf16(acc[nt], ah0, ah1, ah2, ah3, bh0, bh1);
                mma_bf16(acc[nt], ah0, ah1, ah2, ah3, bl0, bl1);
                mma_bf16(acc[nt], al0, al1, al2, al3, bh0, bh1);
            }
        }
        __syncthreads();
    }

    // ---- epilogue: c0,c1 -> row r0; c2,c3 -> row r1 ----
#pragma unroll
    for (int nt = 0; nt < NT_N; nt++) {
        int col = nt * 8 + tig * 2;
        if (r0 < N)
            *reinterpret_cast<float2*>(&sup[(size_t)r0 * OUT_F + col]) =
                make_float2(acc[nt].x, acc[nt].y);
        if (r1 < N)
            *reinterpret_cast<float2*>(&sup[(size_t)r1 * OUT_F + col]) =
                make_float2(acc[nt].z, acc[nt].w);
    }
}

// ==================== CSR build (verbatim R3) ====================
__global__ void zero_counts_kernel(int* __restrict__ counts, int N) {
    int i = blockIdx.x * blockDim.x + threadIdx.x;
    if (i < N) counts[i] = 0;
}

__global__ void hist_kernel(const int* __restrict__ dst, int* __restrict__ counts, int E) {
    int e = blockIdx.x * blockDim.x + threadIdx.x;
    if (e < E) atomicAdd(&counts[dst[e]], 1);
}

__global__ __launch_bounds__(SCAN_B) void scan_block_kernel(
    const int* __restrict__ counts, int* __restrict__ offs,
    int* __restrict__ blksum, int N)
{
    __shared__ int sh[SCAN_B];
    int gid = blockIdx.x * SCAN_B + threadIdx.x;
    int v = (gid < N) ? counts[gid] : 0;
    sh[threadIdx.x] = v;
    __syncthreads();
#pragma unroll
    for (int d = 1; d < SCAN_B; d <<= 1) {
        int t = (threadIdx.x >= d) ? sh[threadIdx.x - d] : 0;
        __syncthreads();
        sh[threadIdx.x] += t;
        __syncthreads();
    }
    if (gid < N) offs[gid] = sh[threadIdx.x] - v;
    if (threadIdx.x == SCAN_B - 1) blksum[blockIdx.x] = sh[SCAN_B - 1];
}

__global__ __launch_bounds__(256) void scan_top_kernel(int* __restrict__ blksum, int nb) {
    __shared__ int sh[256];
    int v = (threadIdx.x < nb) ? blksum[threadIdx.x] : 0;
    sh[threadIdx.x] = v;
    __syncthreads();
#pragma unroll
    for (int d = 1; d < 256; d <<= 1) {
        int t = (threadIdx.x >= d) ? sh[threadIdx.x - d] : 0;
        __syncthreads();
        sh[threadIdx.x] += t;
        __syncthreads();
    }
    if (threadIdx.x < nb) blksum[threadIdx.x] = sh[threadIdx.x] - v;
}

__global__ void scan_add_kernel(int* __restrict__ offs, const int* __restrict__ blksum,
                                int* __restrict__ cursor, int N)
{
    int gid = blockIdx.x * blockDim.x + threadIdx.x;
    if (gid < N) {
        int o = offs[gid] + blksum[gid / SCAN_B];
        offs[gid] = o;
        cursor[gid] = o;
    }
}

__global__ void sort_scatter_kernel(
    const int* __restrict__ src, const int* __restrict__ dst,
    const float* __restrict__ ew, int* __restrict__ cursor,
    unsigned long long* __restrict__ es, int E)
{
    int e = blockIdx.x * blockDim.x + threadIdx.x;
    if (e < E) {
        int d = dst[e];
        int pos = atomicAdd(&cursor[d], 1);
        unsigned long long p = (unsigned int)src[e]
            | ((unsigned long long)__float_as_uint(ew[e]) << 32);
        es[pos] = p;
    }
}

// ==================== gather + relu (verbatim R3) ====================
__global__ __launch_bounds__(256) void gather_kernel(
    const float* __restrict__ sup,
    const unsigned long long* __restrict__ es,
    const int* __restrict__ offs, const int* __restrict__ counts,
    float* __restrict__ out, int N)
{
    int group = threadIdx.x >> 4;
    int lane  = threadIdx.x & 15;
    int node = blockIdx.x * 16 + group;
    if (node >= N) return;

    int start = offs[node];
    int deg   = counts[node];
    int end   = start + deg;

    float4 acc = make_float4(0.f, 0.f, 0.f, 0.f);

    int e = start;
    for (; e + 2 <= end; e += 2) {
        unsigned long long p0 = __ldg(&es[e]);
        unsigned long long p1 = __ldg(&es[e + 1]);
        int   s0 = (int)(unsigned int)p0;
        float w0 = __uint_as_float((unsigned int)(p0 >> 32));
        int   s1 = (int)(unsigned int)p1;
        float w1 = __uint_as_float((unsigned int)(p1 >> 32));
        float4 v0 = *reinterpret_cast<const float4*>(&sup[(size_t)s0 * OUT_F + lane * 4]);
        float4 v1 = *reinterpret_cast<const float4*>(&sup[(size_t)s1 * OUT_F + lane * 4]);
        acc.x = fmaf(v0.x, w0, acc.x);
        acc.y = fmaf(v0.y, w0, acc.y);
        acc.z = fmaf(v0.z, w0, acc.z);
        acc.w = fmaf(v0.w, w0, acc.w);
        acc.x = fmaf(v1.x, w1, acc.x);
        acc.y = fmaf(v1.y, w1, acc.y);
        acc.z = fmaf(v1.z, w1, acc.z);
        acc.w = fmaf(v1.w, w1, acc.w);
    }
    if (e < end) {
        unsigned long long p0 = __ldg(&es[e]);
        int   s0 = (int)(unsigned int)p0;
        float w0 = __uint_as_float((unsigned int)(p0 >> 32));
        float4 v0 = *reinterpret_cast<const float4*>(&sup[(size_t)s0 * OUT_F + lane * 4]);
        acc.x = fmaf(v0.x, w0, acc.x);
        acc.y = fmaf(v0.y, w0, acc.y);
        acc.z = fmaf(v0.z, w0, acc.z);
        acc.w = fmaf(v0.w, w0, acc.w);
    }

    acc.x = fmaxf(acc.x, 0.f);
    acc.y = fmaxf(acc.y, 0.f);
    acc.z = fmaxf(acc.z, 0.f);
    acc.w = fmaxf(acc.w, 0.f);
    *reinterpret_cast<float4*>(&out[(size_t)node * OUT_F + lane * 4]) = acc;
}

extern "C" void kernel_launch(void* const* d_in, const int* in_sizes, int n_in,
                              void* d_out, int out_size)
{
    const float* x    = (const float*)d_in[0];
    const float* w    = (const float*)d_in[1];
    const int*   src  = (const int*)d_in[2];
    const int*   dst  = (const int*)d_in[3];
    const float* ew   = (const float*)d_in[4];
    float* out = (float*)d_out;

    const int N = in_sizes[0] / IN_F;
    const int E = in_sizes[2];

    float* sup;                cudaGetSymbolAddress((void**)&sup, g_support);
    unsigned long long* es;    cudaGetSymbolAddress((void**)&es, g_edges);
    int* counts;               cudaGetSymbolAddress((void**)&counts, g_counts);
    int* offs;                 cudaGetSymbolAddress((void**)&offs, g_offs);
    int* cursor;               cudaGetSymbolAddress((void**)&cursor, g_cursor);
    int* blksum;               cudaGetSymbolAddress((void**)&blksum, g_blksum);

    const int nb = (N + SCAN_B - 1) / SCAN_B;

    // 1) GEMM (bf16 split-3 mma.sync, double-buffered A)
    cudaFuncSetAttribute(gemm_mma_kernel,
                         cudaFuncAttributeMaxDynamicSharedMemorySize, SMEM_TOTAL);
    gemm_mma_kernel<<<(N + ROWS_CTA - 1) / ROWS_CTA, 512, SMEM_TOTAL>>>(x, w, sup, N);

    // 2) CSR build
    zero_counts_kernel<<<(N + 255) / 256, 256>>>(counts, N);
    hist_kernel<<<(E + 255) / 256, 256>>>(dst, counts, E);
    scan_block_kernel<<<nb, SCAN_B>>>(counts, offs, blksum, N);
    scan_top_kernel<<<1, 256>>>(blksum, nb);
    scan_add_kernel<<<(N + 255) / 256, 256>>>(offs, blksum, cursor, N);
    sort_scatter_kernel<<<(E + 255) / 256, 256>>>(src, dst, ew, cursor, es, E);

    // 3) gather + relu
    gather_kernel<<<(N + 15) / 16, 256>>>(sup, es, offs, counts, out, N);
}

// round 9
// speedup vs baseline: 2.7704x; 1.0556x over previous
#include <cuda_runtime.h>
#include <cuda_bf16.h>
#include <cstdint>

// GraphConvolution: out = relu(segment_sum((x @ W)[src] * ew, dst))
// R9 changes vs R8 (125.7us):
//  - hist fused into GEMM kernel as tail-filler blocks; zero_counts dropped
//    (scan_add restores counts=0 after use; offs gets sentinel offs[N]=E)
//  - warp-shuffle scans (2 barriers instead of 18)
//  - gather unrolled x4 for MLP

#define N_NODES_MAX 100000
#define E_MAX       1600000
#define IN_F 256
#define OUT_F 64

#define SCAN_B 512
#define NBLK_MAX ((N_NODES_MAX + SCAN_B - 1) / SCAN_B)

__device__ float              g_support[N_NODES_MAX * OUT_F];
__device__ unsigned long long g_edges[E_MAX];
__device__ int                g_counts[N_NODES_MAX];
__device__ int                g_offs[N_NODES_MAX + 1];
__device__ int                g_cursor[N_NODES_MAX];
__device__ int                g_blksum[NBLK_MAX];

// ==================== helpers ====================
__device__ __forceinline__ uint32_t smem_u32(const void* p) {
    uint32_t a;
    asm("{ .reg .u64 t; cvta.to.shared.u64 t, %1; cvt.u32.u64 %0, t; }"
        : "=r"(a) : "l"(p));
    return a;
}

__device__ __forceinline__ void cp_async16(uint32_t dst, const void* src, int src_bytes) {
    asm volatile("cp.async.cg.shared.global [%0], [%1], 16, %2;"
                 :: "r"(dst), "l"(src), "r"(src_bytes));
}
#define CP_COMMIT() asm volatile("cp.async.commit_group;" ::: "memory")
#define CP_WAIT(n)  asm volatile("cp.async.wait_group %0;" :: "n"(n) : "memory")

__device__ __forceinline__ uint32_t bf2(float x, float y) {
    __nv_bfloat162 h = __floats2bfloat162_rn(x, y);
    return *reinterpret_cast<uint32_t*>(&h);
}
__device__ __forceinline__ float2 bf2f(uint32_t u) {
    __nv_bfloat162 h = *reinterpret_cast<__nv_bfloat162*>(&u);
    return __bfloat1622float2(h);
}

__device__ __forceinline__ void mma_bf16(float4& d,
    uint32_t a0, uint32_t a1, uint32_t a2, uint32_t a3,
    uint32_t b0, uint32_t b1)
{
    asm volatile(
        "mma.sync.aligned.m16n8k16.row.col.f32.bf16.bf16.f32 "
        "{%0,%1,%2,%3}, {%4,%5,%6,%7}, {%8,%9}, {%0,%1,%2,%3};"
        : "+f"(d.x), "+f"(d.y), "+f"(d.z), "+f"(d.w)
        : "r"(a0), "r"(a1), "r"(a2), "r"(a3), "r"(b0), "r"(b1));
}

// ==================== GEMM config ====================
#define KC_N   (IN_F / 16)       // 16
#define NT_N   (OUT_F / 8)       // 8
#define BTAB_ENTRIES (KC_N * NT_N * 32)
#define BTAB_BYTES   (BTAB_ENTRIES * 16)      // 65536

#define ROWS_CTA 256
#define KB       64
#define NKB      (IN_F / KB)     // 4
#define KC_PER_B (KB / 16)       // 4
#define ASTRIDE  68
#define ATILE_BYTES (ROWS_CTA * ASTRIDE * 4)  // 69632
#define SMEM_TOTAL (BTAB_BYTES + 2 * ATILE_BYTES) // 204800

#define HIST_BLOCKS 148

// ==================== GEMM (+ tail hist blocks) ====================
__global__ __launch_bounds__(512, 1) void gemm_hist_kernel(
    const float* __restrict__ x, const float* __restrict__ w,
    float* __restrict__ sup, int N,
    const int* __restrict__ dst, int* __restrict__ counts, int E,
    int gemm_blocks)
{
    const int tid  = threadIdx.x;

    // ---- hist role (tail-filler blocks) ----
    if ((int)blockIdx.x >= gemm_blocks) {
        int b = blockIdx.x - gemm_blocks;
        for (int e = b * 512 + tid; e < E; e += HIST_BLOCKS * 512)
            atomicAdd(&counts[dst[e]], 1);
        return;
    }

    extern __shared__ char smem_raw[];
    float4* Bs = reinterpret_cast<float4*>(smem_raw);
    float*  As = reinterpret_cast<float*>(smem_raw + BTAB_BYTES);
    const uint32_t a_sbase = smem_u32(As);

    const int wid  = tid >> 5;
    const int lane = tid & 31;
    const int g    = lane >> 2;
    const int tig  = lane & 3;

    const int row0  = blockIdx.x * ROWS_CTA;
    const int rloc0 = wid * 16 + g;
    const int rloc1 = rloc0 + 8;
    const int r0 = row0 + rloc0;
    const int r1 = row0 + rloc1;

    auto stage = [&](int kb, int buf) {
        uint32_t abase = a_sbase + buf * ATILE_BYTES;
#pragma unroll
        for (int i = 0; i < 8; i++) {
            int idx = tid + i * 512;
            int r  = idx >> 4;
            int c4 = idx & 15;
            int grow = row0 + r;
            uint32_t d = abase + (uint32_t)(r * ASTRIDE + c4 * 4) * 4u;
            const float* srcp = &x[(size_t)(grow < N ? grow : 0) * IN_F + kb * KB + c4 * 4];
            cp_async16(d, srcp, grow < N ? 16 : 0);
        }
    };

    for (int idx = tid; idx < BTAB_ENTRIES; idx += 512) {
        int ln = idx & 31;
        int nt = (idx >> 5) & 7;
        int kc = idx >> 8;
        int gg  = ln >> 2;
        int tt  = ln & 3;
        int n  = nt * 8 + gg;
        int k0 = kc * 16 + 2 * tt;
        float w00 = w[(size_t)k0 * OUT_F + n];
        float w01 = w[(size_t)(k0 + 1) * OUT_F + n];
        float w10 = w[(size_t)(k0 + 8) * OUT_F + n];
        float w11 = w[(size_t)(k0 + 9) * OUT_F + n];
        uint32_t h0 = bf2(w00, w01);
        uint32_t h1 = bf2(w10, w11);
        float2 hf0 = bf2f(h0);
        float2 hf1 = bf2f(h1);
        uint32_t l0 = bf2(w00 - hf0.x, w01 - hf0.y);
        uint32_t l1 = bf2(w10 - hf1.x, w11 - hf1.y);
        Bs[idx] = make_float4(__uint_as_float(h0), __uint_as_float(h1),
                              __uint_as_float(l0), __uint_as_float(l1));
    }

    float4 acc[NT_N];
#pragma unroll
    for (int nt = 0; nt < NT_N; nt++) acc[nt] = make_float4(0.f, 0.f, 0.f, 0.f);

    stage(0, 0);
    CP_COMMIT();
    __syncthreads();

    for (int kb = 0; kb < NKB; kb++) {
        if (kb + 1 < NKB) {
            stage(kb + 1, (kb + 1) & 1);
            CP_COMMIT();
            CP_WAIT(1);
        } else {
            CP_WAIT(0);
        }
        __syncthreads();

        const float* Ab = As + (kb & 1) * (ROWS_CTA * ASTRIDE);

#pragma unroll
        for (int kcl = 0; kcl < KC_PER_B; kcl++) {
            const int kc = kb * KC_PER_B + kcl;
            const int c0 = kcl * 16 + 2 * tig;

            float2 a00 = *reinterpret_cast<const float2*>(&Ab[rloc0 * ASTRIDE + c0]);
            float2 a08 = *reinterpret_cast<const float2*>(&Ab[rloc0 * ASTRIDE + c0 + 8]);
            float2 a10 = *reinterpret_cast<const float2*>(&Ab[rloc1 * ASTRIDE + c0]);
            float2 a18 = *reinterpret_cast<const float2*>(&Ab[rloc1 * ASTRIDE + c0 + 8]);

            uint32_t ah0 = bf2(a00.x, a00.y);
            uint32_t ah1 = bf2(a10.x, a10.y);
            uint32_t ah2 = bf2(a08.x, a08.y);
            uint32_t ah3 = bf2(a18.x, a18.y);
            float2 f0 = bf2f(ah0), f1 = bf2f(ah1), f2 = bf2f(ah2), f3 = bf2f(ah3);
            uint32_t al0 = bf2(a00.x - f0.x, a00.y - f0.y);
            uint32_t al1 = bf2(a10.x - f1.x, a10.y - f1.y);
            uint32_t al2 = bf2(a08.x - f2.x, a08.y - f2.y);
            uint32_t al3 = bf2(a18.x - f3.x, a18.y - f3.y);

            const float4* brow = &Bs[(kc * NT_N) * 32 + lane];
#pragma unroll
            for (int nt = 0; nt < NT_N; nt++) {
                float4 b = brow[nt * 32];
                uint32_t bh0 = __float_as_uint(b.x);
                uint32_t bh1 = __float_as_uint(b.y);
                uint32_t bl0 = __float_as_uint(b.z);
                uint32_t bl1 = __float_as_uint(b.w);
                mma_bf16(acc[nt], ah0, ah1, ah2, ah3, bh0, bh1);
                mma_bf16(acc[nt], ah0, ah1, ah2, ah3, bl0, bl1);
                mma_bf16(acc[nt], al0, al1, al2, al3, bh0, bh1);
            }
        }
        __syncthreads();
    }

#pragma unroll
    for (int nt = 0; nt < NT_N; nt++) {
        int col = nt * 8 + tig * 2;
        if (r0 < N)
            *reinterpret_cast<float2*>(&sup[(size_t)r0 * OUT_F + col]) =
                make_float2(acc[nt].x, acc[nt].y);
        if (r1 < N)
            *reinterpret_cast<float2*>(&sup[(size_t)r1 * OUT_F + col]) =
                make_float2(acc[nt].z, acc[nt].w);
    }
}

// ==================== warp-shuffle scans ====================
__global__ __launch_bounds__(SCAN_B) void scan_block_kernel(
    const int* __restrict__ counts, int* __restrict__ offs,
    int* __restrict__ blksum, int N)
{
    __shared__ int wsum[16];
    const int lane = threadIdx.x & 31;
    const int wid  = threadIdx.x >> 5;
    int gid = blockIdx.x * SCAN_B + threadIdx.x;
    int v = (gid < N) ? counts[gid] : 0;
    int inc = v;
#pragma unroll
    for (int d = 1; d < 32; d <<= 1) {
        int t = __shfl_up_sync(0xFFFFFFFF, inc, d);
        if (lane >= d) inc += t;
    }
    if (lane == 31) wsum[wid] = inc;
    __syncthreads();
    if (wid == 0) {
        int s = (lane < 16) ? wsum[lane] : 0;
#pragma unroll
        for (int d = 1; d < 16; d <<= 1) {
            int t = __shfl_up_sync(0xFFFFFFFF, s, d);
            if (lane >= d) s += t;
        }
        if (lane < 16) wsum[lane] = s;
    }
    __syncthreads();
    int base = (wid > 0) ? wsum[wid - 1] : 0;
    if (gid < N) offs[gid] = base + inc - v;     // exclusive within block
    if (threadIdx.x == SCAN_B - 1) blksum[blockIdx.x] = wsum[15];
}

__global__ __launch_bounds__(256) void scan_top_kernel(int* __restrict__ blksum, int nb) {
    __shared__ int wsum[8];
    const int lane = threadIdx.x & 31;
    const int wid  = threadIdx.x >> 5;
    int v = ((int)threadIdx.x < nb) ? blksum[threadIdx.x] : 0;
    int inc = v;
#pragma unroll
    for (int d = 1; d < 32; d <<= 1) {
        int t = __shfl_up_sync(0xFFFFFFFF, inc, d);
        if (lane >= d) inc += t;
    }
    if (lane == 31) wsum[wid] = inc;
    __syncthreads();
    if (wid == 0) {
        int s = (lane < 8) ? wsum[lane] : 0;
#pragma unroll
        for (int d = 1; d < 8; d <<= 1) {
            int t = __shfl_up_sync(0xFFFFFFFF, s, d);
            if (lane >= d) s += t;
        }
        if (lane < 8) wsum[lane] = s;
    }
    __syncthreads();
    int base = (wid > 0) ? wsum[wid - 1] : 0;
    if ((int)threadIdx.x < nb) blksum[threadIdx.x] = base + inc - v;  // exclusive
}

__global__ void scan_add_kernel(int* __restrict__ offs, const int* __restrict__ blksum,
                                int* __restrict__ cursor, int* __restrict__ counts,
                                int N, int E)
{
    int gid = blockIdx.x * blockDim.x + threadIdx.x;
    if (gid < N) {
        int o = offs[gid] + blksum[gid / SCAN_B];
        offs[gid] = o;
        cursor[gid] = o;
        counts[gid] = 0;            // restore for next launch (hist assumes zero)
    }
    if (gid == 0) offs[N] = E;      // sentinel for degree computation
}

__global__ void sort_scatter_kernel(
    const int* __restrict__ src, const int* __restrict__ dst,
    const float* __restrict__ ew, int* __restrict__ cursor,
    unsigned long long* __restrict__ es, int E)
{
    int e = blockIdx.x * blockDim.x + threadIdx.x;
    if (e < E) {
        int d = dst[e];
        int pos = atomicAdd(&cursor[d], 1);
        unsigned long long p = (unsigned int)src[e]
            | ((unsigned long long)__float_as_uint(ew[e]) << 32);
        es[pos] = p;
    }
}

// ==================== gather + relu : 16 lanes/node, unroll x4 ====================
__global__ __launch_bounds__(256) void gather_kernel(
    const float* __restrict__ sup,
    const unsigned long long* __restrict__ es,
    const int* __restrict__ offs,
    float* __restrict__ out, int N)
{
    int group = threadIdx.x >> 4;
    int lane  = threadIdx.x & 15;
    int node = blockIdx.x * 16 + group;
    if (node >= N) return;

    int start = offs[node];
    int end   = offs[node + 1];

    float4 acc = make_float4(0.f, 0.f, 0.f, 0.f);

    int e = start;
    for (; e + 4 <= end; e += 4) {
        unsigned long long p0 = __ldg(&es[e]);
        unsigned long long p1 = __ldg(&es[e + 1]);
        unsigned long long p2 = __ldg(&es[e + 2]);
        unsigned long long p3 = __ldg(&es[e + 3]);
        int   s0 = (int)(unsigned int)p0;  float w0 = __uint_as_float((unsigned int)(p0 >> 32));
        int   s1 = (int)(unsigned int)p1;  float w1 = __uint_as_float((unsigned int)(p1 >> 32));
        int   s2 = (int)(unsigned int)p2;  float w2 = __uint_as_float((unsigned int)(p2 >> 32));
        int   s3 = (int)(unsigned int)p3;  float w3 = __uint_as_float((unsigned int)(p3 >> 32));
        float4 v0 = *reinterpret_cast<const float4*>(&sup[(size_t)s0 * OUT_F + lane * 4]);
        float4 v1 = *reinterpret_cast<const float4*>(&sup[(size_t)s1 * OUT_F + lane * 4]);
        float4 v2 = *reinterpret_cast<const float4*>(&sup[(size_t)s2 * OUT_F + lane * 4]);
        float4 v3 = *reinterpret_cast<const float4*>(&sup[(size_t)s3 * OUT_F + lane * 4]);
        acc.x = fmaf(v0.x, w0, acc.x); acc.y = fmaf(v0.y, w0, acc.y);
        acc.z = fmaf(v0.z, w0, acc.z); acc.w = fmaf(v0.w, w0, acc.w);
        acc.x = fmaf(v1.x, w1, acc.x); acc.y = fmaf(v1.y, w1, acc.y);
        acc.z = fmaf(v1.z, w1, acc.z); acc.w = fmaf(v1.w, w1, acc.w);
        acc.x = fmaf(v2.x, w2, acc.x); acc.y = fmaf(v2.y, w2, acc.y);
        acc.z = fmaf(v2.z, w2, acc.z); acc.w = fmaf(v2.w, w2, acc.w);
        acc.x = fmaf(v3.x, w3, acc.x); acc.y = fmaf(v3.y, w3, acc.y);
        acc.z = fmaf(v3.z, w3, acc.z); acc.w = fmaf(v3.w, w3, acc.w);
    }
    for (; e < end; e++) {
        unsigned long long p0 = __ldg(&es[e]);
        int   s0 = (int)(unsigned int)p0;
        float w0 = __uint_as_float((unsigned int)(p0 >> 32));
        float4 v0 = *reinterpret_cast<const float4*>(&sup[(size_t)s0 * OUT_F + lane * 4]);
        acc.x = fmaf(v0.x, w0, acc.x); acc.y = fmaf(v0.y, w0, acc.y);
        acc.z = fmaf(v0.z, w0, acc.z); acc.w = fmaf(v0.w, w0, acc.w);
    }

    acc.x = fmaxf(acc.x, 0.f);
    acc.y = fmaxf(acc.y, 0.f);
    acc.z = fmaxf(acc.z, 0.f);
    acc.w = fmaxf(acc.w, 0.f);
    *reinterpret_cast<float4*>(&out[(size_t)node * OUT_F + lane * 4]) = acc;
}

extern "C" void kernel_launch(void* const* d_in, const int* in_sizes, int n_in,
                              void* d_out, int out_size)
{
    const float* x    = (const float*)d_in[0];
    const float* w    = (const float*)d_in[1];
    const int*   src  = (const int*)d_in[2];
    const int*   dst  = (const int*)d_in[3];
    const float* ew   = (const float*)d_in[4];
    float* out = (float*)d_out;

    const int N = in_sizes[0] / IN_F;
    const int E = in_sizes[2];

    float* sup;                cudaGetSymbolAddress((void**)&sup, g_support);
    unsigned long long* es;    cudaGetSymbolAddress((void**)&es, g_edges);
    int* counts;               cudaGetSymbolAddress((void**)&counts, g_counts);
    int* offs;                 cudaGetSymbolAddress((void**)&offs, g_offs);
    int* cursor;               cudaGetSymbolAddress((void**)&cursor, g_cursor);
    int* blksum;               cudaGetSymbolAddress((void**)&blksum, g_blksum);

    const int nb = (N + SCAN_B - 1) / SCAN_B;
    const int gemm_blocks = (N + ROWS_CTA - 1) / ROWS_CTA;

    // 1) GEMM + hist (hist blocks fill GEMM tail wave)
    cudaFuncSetAttribute(gemm_hist_kernel,
                         cudaFuncAttributeMaxDynamicSharedMemorySize, SMEM_TOTAL);
    gemm_hist_kernel<<<gemm_blocks + HIST_BLOCKS, 512, SMEM_TOTAL>>>(
        x, w, sup, N, dst, counts, E, gemm_blocks);

    // 2) scan chain + sort
    scan_block_kernel<<<nb, SCAN_B>>>(counts, offs, blksum, N);
    scan_top_kernel<<<1, 256>>>(blksum, nb);
    scan_add_kernel<<<(N + 255) / 256, 256>>>(offs, blksum, cursor, counts, N, E);
    sort_scatter_kernel<<<(E + 255) / 256, 256>>>(src, dst, ew, cursor, es, E);

    // 3) gather + relu
    gather_kernel<<<(N + 15) / 16, 256>>>(sup, es, offs, out, N);
}

// round 10
// speedup vs baseline: 2.8804x; 1.0397x over previous
#include <cuda_runtime.h>
#include <cuda_bf16.h>
#include <cuda_fp16.h>
#include <cstdint>

// GraphConvolution: out = relu(segment_sum((x @ W)[src] * ew, dst))
// R10 changes vs R9 (119.0us):
//  - support stored fp16 (halves gather L2 traffic); gather is 8 lanes/node
//    with one LDG.128 per lane per edge
//  - scan chain fused into one decoupled-lookback kernel (ticket-ordered);
//    statuses/ticket reset by the GEMM kernel's hist tail blocks
//  - gather end offset taken from cursor[] (post-sort), no sentinel

#define N_NODES_MAX 100000
#define E_MAX       1600000
#define IN_F 256
#define OUT_F 64

#define SCAN_B 512
#define NBLK_MAX ((N_NODES_MAX + SCAN_B - 1) / SCAN_B)

__device__ __half             g_suph[N_NODES_MAX * OUT_F];
__device__ unsigned long long g_edges[E_MAX];
__device__ int                g_counts[N_NODES_MAX];
__device__ int                g_offs[N_NODES_MAX];
__device__ int                g_cursor[N_NODES_MAX];
__device__ unsigned long long g_tilest[NBLK_MAX];   // scan status: flag<<32 | value
__device__ unsigned int       g_ticket;

// ==================== helpers ====================
__device__ __forceinline__ uint32_t smem_u32(const void* p) {
    uint32_t a;
    asm("{ .reg .u64 t; cvta.to.shared.u64 t, %1; cvt.u32.u64 %0, t; }"
        : "=r"(a) : "l"(p));
    return a;
}

__device__ __forceinline__ void cp_async16(uint32_t dst, const void* src, int src_bytes) {
    asm volatile("cp.async.cg.shared.global [%0], [%1], 16, %2;"
                 :: "r"(dst), "l"(src), "r"(src_bytes));
}
#define CP_COMMIT() asm volatile("cp.async.commit_group;" ::: "memory")
#define CP_WAIT(n)  asm volatile("cp.async.wait_group %0;" :: "n"(n) : "memory")

__device__ __forceinline__ uint32_t bf2(float x, float y) {
    __nv_bfloat162 h = __floats2bfloat162_rn(x, y);
    return *reinterpret_cast<uint32_t*>(&h);
}
__device__ __forceinline__ float2 bf2f(uint32_t u) {
    __nv_bfloat162 h = *reinterpret_cast<__nv_bfloat162*>(&u);
    return __bfloat1622float2(h);
}

__device__ __forceinline__ void mma_bf16(float4& d,
    uint32_t a0, uint32_t a1, uint32_t a2, uint32_t a3,
    uint32_t b0, uint32_t b1)
{
    asm volatile(
        "mma.sync.aligned.m16n8k16.row.col.f32.bf16.bf16.f32 "
        "{%0,%1,%2,%3}, {%4,%5,%6,%7}, {%8,%9}, {%0,%1,%2,%3};"
        : "+f"(d.x), "+f"(d.y), "+f"(d.z), "+f"(d.w)
        : "r"(a0), "r"(a1), "r"(a2), "r"(a3), "r"(b0), "r"(b1));
}

// ==================== GEMM config ====================
#define KC_N   (IN_F / 16)       // 16
#define NT_N   (OUT_F / 8)       // 8
#define BTAB_ENTRIES (KC_N * NT_N * 32)
#define BTAB_BYTES   (BTAB_ENTRIES * 16)      // 65536

#define ROWS_CTA 256
#define KB       64
#define NKB      (IN_F / KB)     // 4
#define KC_PER_B (KB / 16)       // 4
#define ASTRIDE  68
#define ATILE_BYTES (ROWS_CTA * ASTRIDE * 4)  // 69632
#define SMEM_TOTAL (BTAB_BYTES + 2 * ATILE_BYTES) // 204800

#define HIST_BLOCKS 148

// ==================== GEMM (+ tail hist blocks) ====================
__global__ __launch_bounds__(512, 1) void gemm_hist_kernel(
    const float* __restrict__ x, const float* __restrict__ w,
    __half* __restrict__ suph, int N,
    const int* __restrict__ dst, int* __restrict__ counts, int E,
    int gemm_blocks)
{
    const int tid  = threadIdx.x;

    // ---- hist role (tail-filler blocks); block 0 also resets scan state ----
    if ((int)blockIdx.x >= gemm_blocks) {
        int b = blockIdx.x - gemm_blocks;
        if (b == 0) {
            for (int i = tid; i < NBLK_MAX; i += 512) g_tilest[i] = 0ULL;
            if (tid == 0) g_ticket = 0u;
        }
        for (int e = b * 512 + tid; e < E; e += HIST_BLOCKS * 512)
            atomicAdd(&counts[dst[e]], 1);
        return;
    }

    extern __shared__ char smem_raw[];
    float4* Bs = reinterpret_cast<float4*>(smem_raw);
    float*  As = reinterpret_cast<float*>(smem_raw + BTAB_BYTES);
    const uint32_t a_sbase = smem_u32(As);

    const int wid  = tid >> 5;
    const int lane = tid & 31;
    const int g    = lane >> 2;
    const int tig  = lane & 3;

    const int row0  = blockIdx.x * ROWS_CTA;
    const int rloc0 = wid * 16 + g;
    const int rloc1 = rloc0 + 8;
    const int r0 = row0 + rloc0;
    const int r1 = row0 + rloc1;

    auto stage = [&](int kb, int buf) {
        uint32_t abase = a_sbase + buf * ATILE_BYTES;
#pragma unroll
        for (int i = 0; i < 8; i++) {
            int idx = tid + i * 512;
            int r  = idx >> 4;
            int c4 = idx & 15;
            int grow = row0 + r;
            uint32_t d = abase + (uint32_t)(r * ASTRIDE + c4 * 4) * 4u;
            const float* srcp = &x[(size_t)(grow < N ? grow : 0) * IN_F + kb * KB + c4 * 4];
            cp_async16(d, srcp, grow < N ? 16 : 0);
        }
    };

    for (int idx = tid; idx < BTAB_ENTRIES; idx += 512) {
        int ln = idx & 31;
        int nt = (idx >> 5) & 7;
        int kc = idx >> 8;
        int gg  = ln >> 2;
        int tt  = ln & 3;
        int n  = nt * 8 + gg;
        int k0 = kc * 16 + 2 * tt;
        float w00 = w[(size_t)k0 * OUT_F + n];
        float w01 = w[(size_t)(k0 + 1) * OUT_F + n];
        float w10 = w[(size_t)(k0 + 8) * OUT_F + n];
        float w11 = w[(size_t)(k0 + 9) * OUT_F + n];
        uint32_t h0 = bf2(w00, w01);
        uint32_t h1 = bf2(w10, w11);
        float2 hf0 = bf2f(h0);
        float2 hf1 = bf2f(h1);
        uint32_t l0 = bf2(w00 - hf0.x, w01 - hf0.y);
        uint32_t l1 = bf2(w10 - hf1.x, w11 - hf1.y);
        Bs[idx] = make_float4(__uint_as_float(h0), __uint_as_float(h1),
                              __uint_as_float(l0), __uint_as_float(l1));
    }

    float4 acc[NT_N];
#pragma unroll
    for (int nt = 0; nt < NT_N; nt++) acc[nt] = make_float4(0.f, 0.f, 0.f, 0.f);

    stage(0, 0);
    CP_COMMIT();
    __syncthreads();

    for (int kb = 0; kb < NKB; kb++) {
        if (kb + 1 < NKB) {
            stage(kb + 1, (kb + 1) & 1);
            CP_COMMIT();
            CP_WAIT(1);
        } else {
            CP_WAIT(0);
        }
        __syncthreads();

        const float* Ab = As + (kb & 1) * (ROWS_CTA * ASTRIDE);

#pragma unroll
        for (int kcl = 0; kcl < KC_PER_B; kcl++) {
            const int kc = kb * KC_PER_B + kcl;
            const int c0 = kcl * 16 + 2 * tig;

            float2 a00 = *reinterpret_cast<const float2*>(&Ab[rloc0 * ASTRIDE + c0]);
            float2 a08 = *reinterpret_cast<const float2*>(&Ab[rloc0 * ASTRIDE + c0 + 8]);
            float2 a10 = *reinterpret_cast<const float2*>(&Ab[rloc1 * ASTRIDE + c0]);
            float2 a18 = *reinterpret_cast<const float2*>(&Ab[rloc1 * ASTRIDE + c0 + 8]);

            uint32_t ah0 = bf2(a00.x, a00.y);
            uint32_t ah1 = bf2(a10.x, a10.y);
            uint32_t ah2 = bf2(a08.x, a08.y);
            uint32_t ah3 = bf2(a18.x, a18.y);
            float2 f0 = bf2f(ah0), f1 = bf2f(ah1), f2 = bf2f(ah2), f3 = bf2f(ah3);
            uint32_t al0 = bf2(a00.x - f0.x, a00.y - f0.y);
            uint32_t al1 = bf2(a10.x - f1.x, a10.y - f1.y);
            uint32_t al2 = bf2(a08.x - f2.x, a08.y - f2.y);
            uint32_t al3 = bf2(a18.x - f3.x, a18.y - f3.y);

            const float4* brow = &Bs[(kc * NT_N) * 32 + lane];
#pragma unroll
            for (int nt = 0; nt < NT_N; nt++) {
                float4 b = brow[nt * 32];
                uint32_t bh0 = __float_as_uint(b.x);
                uint32_t bh1 = __float_as_uint(b.y);
                uint32_t bl0 = __float_as_uint(b.z);
                uint32_t bl1 = __float_as_uint(b.w);
                mma_bf16(acc[nt], ah0, ah1, ah2, ah3, bh0, bh1);
                mma_bf16(acc[nt], ah0, ah1, ah2, ah3, bl0, bl1);
                mma_bf16(acc[nt], al0, al1, al2, al3, bh0, bh1);
            }
        }
        __syncthreads();
    }

    // ---- epilogue: store fp16 support ----
#pragma unroll
    for (int nt = 0; nt < NT_N; nt++) {
        int col = nt * 8 + tig * 2;
        if (r0 < N) {
            __half2 h = __floats2half2_rn(acc[nt].x, acc[nt].y);
            *reinterpret_cast<__half2*>(&suph[(size_t)r0 * OUT_F + col]) = h;
        }
        if (r1 < N) {
            __half2 h = __floats2half2_rn(acc[nt].z, acc[nt].w);
            *reinterpret_cast<__half2*>(&suph[(size_t)r1 * OUT_F + col]) = h;
        }
    }
}

// ==================== fused scan (decoupled lookback, one kernel) ==============
__global__ __launch_bounds__(SCAN_B) void scan_fused_kernel(
    int* __restrict__ counts, int* __restrict__ offs,
    int* __restrict__ cursor, int N)
{
    __shared__ int sbid;
    __shared__ int wsum[16];
    __shared__ int sprefix;

    const int tid  = threadIdx.x;
    const int lane = tid & 31;
    const int wid  = tid >> 5;

    if (tid == 0) sbid = (int)atomicAdd(&g_ticket, 1u);
    __syncthreads();
    const int bid = sbid;
    const int gid = bid * SCAN_B + tid;

    int v = (gid < N) ? counts[gid] : 0;
    int inc = v;
#pragma unroll
    for (int d = 1; d < 32; d <<= 1) {
        int t = __shfl_up_sync(0xFFFFFFFF, inc, d);
        if (lane >= d) inc += t;
    }
    if (lane == 31) wsum[wid] = inc;
    __syncthreads();
    if (wid == 0) {
        int s = (lane < 16) ? wsum[lane] : 0;
#pragma unroll
        for (int d = 1; d < 16; d <<= 1) {
            int t = __shfl_up_sync(0xFFFFFFFF, s, d);
            if (lane >= d) s += t;
        }
        if (lane < 16) wsum[lane] = s;
    }
    __syncthreads();
    const int block_total = wsum[15];

    if (tid == 0) {
        if (bid == 0) {
            atomicExch(&g_tilest[0], (2ULL << 32) | (unsigned)block_total);
            sprefix = 0;
        } else {
            atomicExch(&g_tilest[bid], (1ULL << 32) | (unsigned)block_total);
            int prefix = 0;
            int p = bid - 1;
            while (true) {
                unsigned long long s = atomicAdd(&g_tilest[p], 0ULL);
                unsigned flag = (unsigned)(s >> 32);
                if (flag == 2u) { prefix += (int)(unsigned)s; break; }
                if (flag == 1u) { prefix += (int)(unsigned)s; p--; }
            }
            atomicExch(&g_tilest[bid],
                       (2ULL << 32) | (unsigned)(prefix + block_total));
            sprefix = prefix;
        }
    }
    __syncthreads();

    const int base = sprefix + ((wid > 0) ? wsum[wid - 1] : 0);
    if (gid < N) {
        int o = base + inc - v;
        offs[gid]   = o;
        cursor[gid] = o;
        counts[gid] = 0;   // restore for next launch
    }
}

__global__ void sort_scatter_kernel(
    const int* __restrict__ src, const int* __restrict__ dst,
    const float* __restrict__ ew, int* __restrict__ cursor,
    unsigned long long* __restrict__ es, int E)
{
    int e = blockIdx.x * blockDim.x + threadIdx.x;
    if (e < E) {
        int d = dst[e];
        int pos = atomicAdd(&cursor[d], 1);
        unsigned long long p = (unsigned int)src[e]
            | ((unsigned long long)__float_as_uint(ew[e]) << 32);
        es[pos] = p;
    }
}

// ==================== gather + relu : 8 lanes/node, fp16 sup, unroll x4 =========
__global__ __launch_bounds__(256) void gather_kernel(
    const __half* __restrict__ suph,
    const unsigned long long* __restrict__ es,
    const int* __restrict__ offs, const int* __restrict__ cursor,
    float* __restrict__ out, int N)
{
    int group = threadIdx.x >> 3;          // 32 nodes per block
    int lane  = threadIdx.x & 7;           // 8 halves each
    int node = blockIdx.x * 32 + group;
    if (node >= N) return;

    int start = offs[node];
    int end   = cursor[node];              // post-sort cursor == end offset

    float acc[8];
#pragma unroll
    for (int i = 0; i < 8; i++) acc[i] = 0.f;

    auto fma_edge = [&](unsigned long long p) {
        int   s = (int)(unsigned int)p;
        float wgt = __uint_as_float((unsigned int)(p >> 32));
        uint4 v = *reinterpret_cast<const uint4*>(&suph[(size_t)s * OUT_F + lane * 8]);
        float2 f0 = __half22float2(*reinterpret_cast<__half2*>(&v.x));
        float2 f1 = __half22float2(*reinterpret_cast<__half2*>(&v.y));
        float2 f2 = __half22float2(*reinterpret_cast<__half2*>(&v.z));
        float2 f3 = __half22float2(*reinterpret_cast<__half2*>(&v.w));
        acc[0] = fmaf(f0.x, wgt, acc[0]); acc[1] = fmaf(f0.y, wgt, acc[1]);
        acc[2] = fmaf(f1.x, wgt, acc[2]); acc[3] = fmaf(f1.y, wgt, acc[3]);
        acc[4] = fmaf(f2.x, wgt, acc[4]); acc[5] = fmaf(f2.y, wgt, acc[5]);
        acc[6] = fmaf(f3.x, wgt, acc[6]); acc[7] = fmaf(f3.y, wgt, acc[7]);
    };

    int e = start;
    for (; e + 4 <= end; e += 4) {
        unsigned long long p0 = __ldg(&es[e]);
        unsigned long long p1 = __ldg(&es[e + 1]);
        unsigned long long p2 = __ldg(&es[e + 2]);
        unsigned long long p3 = __ldg(&es[e + 3]);
        fma_edge(p0); fma_edge(p1); fma_edge(p2); fma_edge(p3);
    }
    for (; e < end; e++) fma_edge(__ldg(&es[e]));

    float4 o0 = make_float4(fmaxf(acc[0], 0.f), fmaxf(acc[1], 0.f),
                            fmaxf(acc[2], 0.f), fmaxf(acc[3], 0.f));
    float4 o1 = make_float4(fmaxf(acc[4], 0.f), fmaxf(acc[5], 0.f),
                            fmaxf(acc[6], 0.f), fmaxf(acc[7], 0.f));
    float* op = &out[(size_t)node * OUT_F + lane * 8];
    *reinterpret_cast<float4*>(op)     = o0;
    *reinterpret_cast<float4*>(op + 4) = o1;
}

extern "C" void kernel_launch(void* const* d_in, const int* in_sizes, int n_in,
                              void* d_out, int out_size)
{
    const float* x    = (const float*)d_in[0];
    const float* w    = (const float*)d_in[1];
    const int*   src  = (const int*)d_in[2];
    const int*   dst  = (const int*)d_in[3];
    const float* ew   = (const float*)d_in[4];
    float* out = (float*)d_out;

    const int N = in_sizes[0] / IN_F;
    const int E = in_sizes[2];

    __half* suph;              cudaGetSymbolAddress((void**)&suph, g_suph);
    unsigned long long* es;    cudaGetSymbolAddress((void**)&es, g_edges);
    int* counts;               cudaGetSymbolAddress((void**)&counts, g_counts);
    int* offs;                 cudaGetSymbolAddress((void**)&offs, g_offs);
    int* cursor;               cudaGetSymbolAddress((void**)&cursor, g_cursor);

    const int nb = (N + SCAN_B - 1) / SCAN_B;
    const int gemm_blocks = (N + ROWS_CTA - 1) / ROWS_CTA;

    // 1) GEMM + hist (+ scan-state reset in hist block 0)
    cudaFuncSetAttribute(gemm_hist_kernel,
                         cudaFuncAttributeMaxDynamicSharedMemorySize, SMEM_TOTAL);
    gemm_hist_kernel<<<gemm_blocks + HIST_BLOCKS, 512, SMEM_TOTAL>>>(
        x, w, suph, N, dst, counts, E, gemm_blocks);

    // 2) fused scan + sort
    scan_fused_kernel<<<nb, SCAN_B>>>(counts, offs, cursor, N);
    sort_scatter_kernel<<<(E + 255) / 256, 256>>>(src, dst, ew, cursor, es, E);

    // 3) gather + relu
    gather_kernel<<<(N + 31) / 32, 256>>>(suph, es, offs, cursor, out, N);
}